// round 1
// baseline (speedup 1.0000x reference)
#include <cuda_runtime.h>
#include <math.h>

// Problem constants
constexpr int BB  = 2;
constexpr int TT  = 2048;
constexpr int DD  = 1024;
constexpr int HH  = 16;
constexpr int LL  = 6;
constexpr int VV  = 50257;
constexpr int TGT = 512;
constexpr int DHH = DD / HH;      // 64
constexpr int BT  = BB * TT;      // 4096
constexpr int FF  = 4 * DD;       // 4096

// ---------------- scratch (device globals; no runtime allocation) ------------
__device__ float g_x  [(size_t)BT * DD];
__device__ float g_h  [(size_t)BT * DD];
__device__ float g_q  [(size_t)BT * DD];
__device__ float g_k  [(size_t)BT * DD];
__device__ float g_v  [(size_t)BT * DD];
__device__ float g_y  [(size_t)BT * DD];
__device__ float g_att[(size_t)BB * HH * TT * TT];   // 512 MB
__device__ float g_ffn[(size_t)BT * FF];             // 64 MB

// ---------------- embedding gather -------------------------------------------
__global__ void embed_kernel(const int* __restrict__ idx,
                             const float4* __restrict__ emb,
                             float4* __restrict__ x)
{
    int i = blockIdx.x * blockDim.x + threadIdx.x;    // over BT * (DD/4)
    int t = i >> 8;                                   // DD/4 = 256
    int d = i & 255;
    int tok = idx[t];
    x[i] = emb[(long long)tok * 256 + d];
}

// ---------------- layernorm (row = 1024, 256 threads, float4) ----------------
__global__ void ln_kernel(const float* __restrict__ x,
                          const float* __restrict__ w,
                          const float* __restrict__ b,
                          float* __restrict__ out)
{
    long long row = blockIdx.x;
    const float4* xr = (const float4*)(x + row * DD);
    float4 xv = xr[threadIdx.x];
    float s  = xv.x + xv.y + xv.z + xv.w;
    float sq = xv.x*xv.x + xv.y*xv.y + xv.z*xv.z + xv.w*xv.w;
#pragma unroll
    for (int o = 16; o; o >>= 1) {
        s  += __shfl_xor_sync(0xffffffffu, s,  o);
        sq += __shfl_xor_sync(0xffffffffu, sq, o);
    }
    __shared__ float ss[8], sqq[8];
    __shared__ float s_mean, s_rstd;
    int wid = threadIdx.x >> 5;
    if ((threadIdx.x & 31) == 0) { ss[wid] = s; sqq[wid] = sq; }
    __syncthreads();
    if (threadIdx.x == 0) {
        float S = 0.f, Q = 0.f;
#pragma unroll
        for (int i = 0; i < 8; i++) { S += ss[i]; Q += sqq[i]; }
        float mean = S / DD;
        float var  = Q / DD - mean * mean;
        s_mean = mean;
        s_rstd = rsqrtf(var + 1e-5f);
    }
    __syncthreads();
    float mean = s_mean, rstd = s_rstd;
    float4 wv = ((const float4*)w)[threadIdx.x];
    float4 bv = ((const float4*)b)[threadIdx.x];
    float4 o;
    o.x = (xv.x - mean) * rstd * wv.x + bv.x;
    o.y = (xv.y - mean) * rstd * wv.y + bv.y;
    o.z = (xv.z - mean) * rstd * wv.z + bv.z;
    o.w = (xv.w - mean) * rstd * wv.w + bv.w;
    ((float4*)(out + row * DD))[threadIdx.x] = o;
}

// ---------------- prefix-masked softmax over rows of att ---------------------
// allowed(i,j) = (j <= i) || (j < TT - TGT + 1)  -> contiguous prefix
__global__ void softmax_kernel(float* __restrict__ att)
{
    long long row = blockIdx.x;                 // B*H*T rows
    int i = (int)(row % TT);
    int jm0 = TT - TGT + 1;                     // 1537
    int jmax = (i + 1 > jm0) ? (i + 1) : jm0;
    float* p = att + row * (long long)TT;

    float vals[8];
    float mx = -1e30f;
#pragma unroll
    for (int s = 0; s < 8; s++) {
        int j = threadIdx.x + s * 256;
        float v = (j < jmax) ? p[j] : -1e30f;
        vals[s] = v;
        mx = fmaxf(mx, v);
    }
#pragma unroll
    for (int o = 16; o; o >>= 1) mx = fmaxf(mx, __shfl_xor_sync(0xffffffffu, mx, o));
    __shared__ float sm1[8], sm2[8];
    __shared__ float s_max, s_sum;
    int wid = threadIdx.x >> 5;
    if ((threadIdx.x & 31) == 0) sm1[wid] = mx;
    __syncthreads();
    if (threadIdx.x == 0) {
        float m = sm1[0];
#pragma unroll
        for (int kk = 1; kk < 8; kk++) m = fmaxf(m, sm1[kk]);
        s_max = m;
    }
    __syncthreads();
    mx = s_max;

    float sum = 0.f;
#pragma unroll
    for (int s = 0; s < 8; s++) {
        int j = threadIdx.x + s * 256;
        float e = (j < jmax) ? __expf(vals[s] - mx) : 0.f;
        vals[s] = e;
        sum += e;
    }
#pragma unroll
    for (int o = 16; o; o >>= 1) sum += __shfl_xor_sync(0xffffffffu, sum, o);
    if ((threadIdx.x & 31) == 0) sm2[wid] = sum;
    __syncthreads();
    if (threadIdx.x == 0) {
        float S = 0.f;
#pragma unroll
        for (int kk = 0; kk < 8; kk++) S += sm2[kk];
        s_sum = S;
    }
    __syncthreads();
    float inv = 1.f / s_sum;
#pragma unroll
    for (int s = 0; s < 8; s++) {
        int j = threadIdx.x + s * 256;
        p[j] = vals[s] * inv;
    }
}

// ---------------- generic tiled fp32 GEMM ------------------------------------
// C[M,N] = alpha * A @ B(^T) + bias[n] + Res  (optional exact-GELU epilogue)
// Batched via blockIdx.z with z = b*Hb + h; per-batch offsets b*s?b + h*s?h.
template<int BM, int BN, int BK, int TM, int TN, bool TRANSB, bool GELU_>
__global__ void gemm_kernel(
    const float* __restrict__ A, int lda, long long sAb, long long sAh,
    const float* __restrict__ B, int ldb, long long sBb, long long sBh,
    float*       __restrict__ C, int ldc, long long sCb, long long sCh,
    const float* __restrict__ bias, const float* __restrict__ Res,
    int M, int N, int K, int Hb, float alpha)
{
    constexpr int NTHREADS = (BM / TM) * (BN / TN);
    int z  = blockIdx.z;
    int bz = z / Hb, hz = z % Hb;
    A += (long long)bz * sAb + (long long)hz * sAh;
    B += (long long)bz * sBb + (long long)hz * sBh;
    C += (long long)bz * sCb + (long long)hz * sCh;
    if (Res) Res += (long long)bz * sCb + (long long)hz * sCh;

    int mBase = blockIdx.y * BM;
    int nBase = blockIdx.x * BN;

    __shared__ float As[BK][BM + 1];
    __shared__ float Bs[BK][BN + 1];

    int tid = threadIdx.x;
    int tx  = tid % (BN / TN);
    int ty  = tid / (BN / TN);

    float acc[TM][TN];
#pragma unroll
    for (int i = 0; i < TM; i++)
#pragma unroll
        for (int j = 0; j < TN; j++) acc[i][j] = 0.f;

    for (int kt = 0; kt < K; kt += BK) {
        // load A tile (transposed into smem)
#pragma unroll
        for (int lin = tid; lin < BM * BK; lin += NTHREADS) {
            int m = lin / BK, kk = lin % BK;
            int gm = mBase + m;
            As[kk][m] = (gm < M) ? A[(long long)gm * lda + kt + kk] : 0.f;
        }
        // load B tile
        if (!TRANSB) {
#pragma unroll
            for (int lin = tid; lin < BK * BN; lin += NTHREADS) {
                int kk = lin / BN, n = lin % BN;
                int gn = nBase + n;
                Bs[kk][n] = (gn < N) ? B[(long long)(kt + kk) * ldb + gn] : 0.f;
            }
        } else {
#pragma unroll
            for (int lin = tid; lin < BK * BN; lin += NTHREADS) {
                int n = lin / BK, kk = lin % BK;
                int gn = nBase + n;
                Bs[kk][n] = (gn < N) ? B[(long long)gn * ldb + kt + kk] : 0.f;
            }
        }
        __syncthreads();

#pragma unroll
        for (int kk = 0; kk < BK; kk++) {
            float a[TM], bb[TN];
#pragma unroll
            for (int i = 0; i < TM; i++) a[i]  = As[kk][ty * TM + i];
#pragma unroll
            for (int j = 0; j < TN; j++) bb[j] = Bs[kk][tx * TN + j];
#pragma unroll
            for (int i = 0; i < TM; i++)
#pragma unroll
                for (int j = 0; j < TN; j++)
                    acc[i][j] = fmaf(a[i], bb[j], acc[i][j]);
        }
        __syncthreads();
    }

    // epilogue
#pragma unroll
    for (int i = 0; i < TM; i++) {
        int gm = mBase + ty * TM + i;
        if (gm >= M) continue;
#pragma unroll
        for (int j = 0; j < TN; j++) {
            int gn = nBase + tx * TN + j;
            if (gn >= N) continue;
            float v = acc[i][j] * alpha;
            if (bias) v += bias[gn];
            if (Res)  v += Res[(long long)gm * ldc + gn];
            if (GELU_) v = 0.5f * v * (1.f + erff(v * 0.70710678118654752f));
            C[(long long)gm * ldc + gn] = v;
        }
    }
}

// ---------------- host-side orchestration ------------------------------------
extern "C" void kernel_launch(void* const* d_in, const int* in_sizes, int n_in,
                              void* d_out, int out_size)
{
    const int*   idx    = (const int*)  d_in[0];
    const float* tokemb = (const float*)d_in[1];
    const float* ln1w   = (const float*)d_in[2];
    const float* ln1b   = (const float*)d_in[3];
    const float* Wq     = (const float*)d_in[4];
    const float* bq     = (const float*)d_in[5];
    const float* Wk     = (const float*)d_in[6];
    const float* bk     = (const float*)d_in[7];
    const float* Wv     = (const float*)d_in[8];
    const float* bv     = (const float*)d_in[9];
    const float* Wp     = (const float*)d_in[10];
    const float* bp     = (const float*)d_in[11];
    const float* ln2w   = (const float*)d_in[12];
    const float* ln2b   = (const float*)d_in[13];
    const float* W1     = (const float*)d_in[14];
    const float* b1     = (const float*)d_in[15];
    const float* W2     = (const float*)d_in[16];
    const float* b2     = (const float*)d_in[17];
    const float* lnfw   = (const float*)d_in[18];
    const float* lnfb   = (const float*)d_in[19];
    const float* headw  = (const float*)d_in[20];
    float* out = (float*)d_out;

    float *x, *h, *q, *k, *v, *y, *att, *ffn;
    cudaGetSymbolAddress((void**)&x,   g_x);
    cudaGetSymbolAddress((void**)&h,   g_h);
    cudaGetSymbolAddress((void**)&q,   g_q);
    cudaGetSymbolAddress((void**)&k,   g_k);
    cudaGetSymbolAddress((void**)&v,   g_v);
    cudaGetSymbolAddress((void**)&y,   g_y);
    cudaGetSymbolAddress((void**)&att, g_att);
    cudaGetSymbolAddress((void**)&ffn, g_ffn);

    // token embedding gather
    embed_kernel<<<BT * (DD / 4) / 256, 256>>>(idx, (const float4*)tokemb, (float4*)x);

    dim3 blk(256);
    for (int l = 0; l < LL; l++) {
        const float* wq = Wq + (long long)l * DD * DD;
        const float* wk = Wk + (long long)l * DD * DD;
        const float* wv = Wv + (long long)l * DD * DD;
        const float* wp = Wp + (long long)l * DD * DD;
        const float* w1 = W1 + (long long)l * DD * FF;
        const float* w2 = W2 + (long long)l * FF * DD;

        // LN1
        ln_kernel<<<BT, 256>>>(x, ln1w + l * DD, ln1b + l * DD, h);

        // QKV projections
        dim3 g1(DD / 128, BT / 128, 1);
        gemm_kernel<128,128,16,8,8,false,false><<<g1, blk>>>(
            h, DD, 0, 0, wq, DD, 0, 0, q, DD, 0, 0,
            bq + l * DD, nullptr, BT, DD, DD, 1, 1.f);
        gemm_kernel<128,128,16,8,8,false,false><<<g1, blk>>>(
            h, DD, 0, 0, wk, DD, 0, 0, k, DD, 0, 0,
            bk + l * DD, nullptr, BT, DD, DD, 1, 1.f);
        gemm_kernel<128,128,16,8,8,false,false><<<g1, blk>>>(
            h, DD, 0, 0, wv, DD, 0, 0, v, DD, 0, 0,
            bv + l * DD, nullptr, BT, DD, DD, 1, 1.f);

        // scores = scale * q @ k^T   (batched over B*H)
        dim3 g2(TT / 128, TT / 128, BB * HH);
        gemm_kernel<128,128,16,8,8,true,false><<<g2, blk>>>(
            q,   DD, (long long)TT * DD, DHH,
            k,   DD, (long long)TT * DD, DHH,
            att, TT, (long long)HH * TT * TT, (long long)TT * TT,
            nullptr, nullptr, TT, TT, DHH, HH, 0.125f);

        // masked softmax (prefix mask)
        softmax_kernel<<<BB * HH * TT, 256>>>(att);

        // y = att @ v   (N = 64 tile variant)
        dim3 g3(1, TT / 128, BB * HH);
        gemm_kernel<128,64,16,8,4,false,false><<<g3, blk>>>(
            att, TT, (long long)HH * TT * TT, (long long)TT * TT,
            v,   DD, (long long)TT * DD, DHH,
            y,   DD, (long long)TT * DD, DHH,
            nullptr, nullptr, TT, DHH, TT, HH, 1.f);

        // x = x + y @ Wp + bp
        gemm_kernel<128,128,16,8,8,false,false><<<g1, blk>>>(
            y, DD, 0, 0, wp, DD, 0, 0, x, DD, 0, 0,
            bp + l * DD, x, BT, DD, DD, 1, 1.f);

        // LN2
        ln_kernel<<<BT, 256>>>(x, ln2w + l * DD, ln2b + l * DD, h);

        // MLP up + exact GELU
        dim3 g4(FF / 128, BT / 128, 1);
        gemm_kernel<128,128,16,8,8,false,true><<<g4, blk>>>(
            h, DD, 0, 0, w1, FF, 0, 0, ffn, FF, 0, 0,
            b1 + (long long)l * FF, nullptr, BT, FF, DD, 1, 1.f);

        // MLP down + residual
        gemm_kernel<128,128,16,8,8,false,false><<<g1, blk>>>(
            ffn, FF, 0, 0, w2, DD, 0, 0, x, DD, 0, 0,
            b2 + l * DD, x, BT, DD, FF, 1, 1.f);
    }

    // final LN
    ln_kernel<<<BT, 256>>>(x, lnfw, lnfb, h);

    // LM head: [BT, D] @ [D, V]
    dim3 g5((VV + 127) / 128, BT / 128, 1);
    gemm_kernel<128,128,16,8,8,false,false><<<g5, blk>>>(
        h, DD, 0, 0, headw, VV, 0, 0, out, VV, 0, 0,
        nullptr, nullptr, BT, VV, DD, 1, 1.f);
}

// round 2
// speedup vs baseline: 3.2253x; 3.2253x over previous
#include <cuda_runtime.h>
#include <mma.h>
#include <math.h>

using namespace nvcuda;

// Problem constants
constexpr int BB  = 2;
constexpr int TT  = 2048;
constexpr int DD  = 1024;
constexpr int HH  = 16;
constexpr int LL  = 6;
constexpr int VV  = 50257;
constexpr int TGT = 512;
constexpr int DHH = DD / HH;      // 64
constexpr int BT  = BB * TT;      // 4096
constexpr int FF  = 4 * DD;       // 4096
constexpr int JM0 = TT - TGT + 1; // 1537 (prefix-mask boundary)

// ---------------- scratch (device globals; no runtime allocation) ------------
__device__ float g_x  [(size_t)BT * DD];
__device__ float g_h  [(size_t)BT * DD];
__device__ float g_q  [(size_t)BT * DD];
__device__ float g_k  [(size_t)BT * DD];
__device__ float g_v  [(size_t)BT * DD];
__device__ float g_y  [(size_t)BT * DD];
__device__ float g_att[(size_t)BB * HH * TT * TT];   // 512 MB
__device__ float g_ffn[(size_t)BT * FF];             // 64 MB

// ---------------- embedding gather -------------------------------------------
__global__ void embed_kernel(const int* __restrict__ idx,
                             const float4* __restrict__ emb,
                             float4* __restrict__ x)
{
    int i = blockIdx.x * blockDim.x + threadIdx.x;    // over BT * (DD/4)
    int t = i >> 8;                                   // DD/4 = 256
    int d = i & 255;
    int tok = idx[t];
    x[i] = emb[(long long)tok * 256 + d];
}

// ---------------- layernorm (row = 1024, 256 threads, float4) ----------------
__global__ void ln_kernel(const float* __restrict__ x,
                          const float* __restrict__ w,
                          const float* __restrict__ b,
                          float* __restrict__ out)
{
    long long row = blockIdx.x;
    const float4* xr = (const float4*)(x + row * DD);
    float4 xv = xr[threadIdx.x];
    float s  = xv.x + xv.y + xv.z + xv.w;
    float sq = xv.x*xv.x + xv.y*xv.y + xv.z*xv.z + xv.w*xv.w;
#pragma unroll
    for (int o = 16; o; o >>= 1) {
        s  += __shfl_xor_sync(0xffffffffu, s,  o);
        sq += __shfl_xor_sync(0xffffffffu, sq, o);
    }
    __shared__ float ss[8], sqq[8];
    __shared__ float s_mean, s_rstd;
    int wid = threadIdx.x >> 5;
    if ((threadIdx.x & 31) == 0) { ss[wid] = s; sqq[wid] = sq; }
    __syncthreads();
    if (threadIdx.x == 0) {
        float S = 0.f, Q = 0.f;
#pragma unroll
        for (int i = 0; i < 8; i++) { S += ss[i]; Q += sqq[i]; }
        float mean = S / DD;
        float var  = Q / DD - mean * mean;
        s_mean = mean;
        s_rstd = rsqrtf(var + 1e-5f);
    }
    __syncthreads();
    float mean = s_mean, rstd = s_rstd;
    float4 wv = ((const float4*)w)[threadIdx.x];
    float4 bv = ((const float4*)b)[threadIdx.x];
    float4 o;
    o.x = (xv.x - mean) * rstd * wv.x + bv.x;
    o.y = (xv.y - mean) * rstd * wv.y + bv.y;
    o.z = (xv.z - mean) * rstd * wv.z + bv.z;
    o.w = (xv.w - mean) * rstd * wv.w + bv.w;
    ((float4*)(out + row * DD))[threadIdx.x] = o;
}

// ---------------- prefix-masked softmax over rows of att ---------------------
// allowed(i,j) = (j <= i) || (j < JM0)  -> contiguous prefix
__global__ void softmax_kernel(float* __restrict__ att)
{
    long long row = blockIdx.x;                 // B*H*T rows
    int i = (int)(row % TT);
    int jmax = (i + 1 > JM0) ? (i + 1) : JM0;
    float* p = att + row * (long long)TT;

    float vals[8];
    float mx = -1e30f;
#pragma unroll
    for (int s = 0; s < 8; s++) {
        int j = threadIdx.x + s * 256;
        float v = (j < jmax) ? p[j] : -1e30f;
        vals[s] = v;
        mx = fmaxf(mx, v);
    }
#pragma unroll
    for (int o = 16; o; o >>= 1) mx = fmaxf(mx, __shfl_xor_sync(0xffffffffu, mx, o));
    __shared__ float sm1[8], sm2[8];
    __shared__ float s_max, s_sum;
    int wid = threadIdx.x >> 5;
    if ((threadIdx.x & 31) == 0) sm1[wid] = mx;
    __syncthreads();
    if (threadIdx.x == 0) {
        float m = sm1[0];
#pragma unroll
        for (int kk = 1; kk < 8; kk++) m = fmaxf(m, sm1[kk]);
        s_max = m;
    }
    __syncthreads();
    mx = s_max;

    float sum = 0.f;
#pragma unroll
    for (int s = 0; s < 8; s++) {
        int j = threadIdx.x + s * 256;
        float e = (j < jmax) ? __expf(vals[s] - mx) : 0.f;
        vals[s] = e;
        sum += e;
    }
#pragma unroll
    for (int o = 16; o; o >>= 1) sum += __shfl_xor_sync(0xffffffffu, sum, o);
    if ((threadIdx.x & 31) == 0) sm2[wid] = sum;
    __syncthreads();
    if (threadIdx.x == 0) {
        float S = 0.f;
#pragma unroll
        for (int kk = 0; kk < 8; kk++) S += sm2[kk];
        s_sum = S;
    }
    __syncthreads();
    float inv = 1.f / s_sum;
#pragma unroll
    for (int s = 0; s < 8; s++) {
        int j = threadIdx.x + s * 256;
        p[j] = vals[s] * inv;   // writes 0 for masked region -> AV GEMM safe
    }
}

// ---------------- tf32 tensor-core GEMM ---------------------------------------
// C[M,N] = alpha * A @ B(^T) + bias[n] + Res  (optional exact-GELU epilogue)
// Batched via blockIdx.z (z = b*Hb + h). cmode: 0 none, 1 skip fully-masked
// score tiles, 2 cap K at causal horizon (AV GEMM).
template<int BM, int BN, int BK, int WM, int WN, bool TRANSB, bool GELU_>
__global__ void __launch_bounds__(256, 2) tc_gemm(
    const float* __restrict__ A, int lda, long long sAb, long long sAh,
    const float* __restrict__ B, int ldb, long long sBb, long long sBh,
    float*       __restrict__ C, int ldc, long long sCb, long long sCh,
    const float* __restrict__ bias, const float* __restrict__ Res,
    int M, int N, int K, int Hb, float alpha, int cmode)
{
    constexpr int WARPS_M = BM / WM;
    constexpr int WARPS_N = BN / WN;
    constexpr int NWARP   = WARPS_M * WARPS_N;
    constexpr int NT      = NWARP * 32;
    constexpr int MF      = WM / 16;
    constexpr int NF      = WN / 16;
    constexpr int LDA_S   = BK + 8;
    constexpr int LDB_S   = BN + 8;
    static_assert(NT == 256, "block size must be 256");

    int mBase = blockIdx.y * BM;
    int nBase = blockIdx.x * BN;

    if (cmode == 1 && nBase >= JM0 && nBase >= mBase + BM) return; // fully masked

    int Keff = K;
    if (cmode == 2) {
        int jm = mBase + BM;                 // causal horizon for this row tile
        if (jm < JM0) jm = JM0;
        jm = (jm + BK - 1) / BK * BK;
        if (jm < Keff) Keff = jm;
    }

    int z  = blockIdx.z;
    int bz = z / Hb, hz = z % Hb;
    A += (long long)bz * sAb + (long long)hz * sAh;
    B += (long long)bz * sBb + (long long)hz * sBh;
    C += (long long)bz * sCb + (long long)hz * sCh;
    if (Res) Res += (long long)bz * sCb + (long long)hz * sCh;

    __shared__ __align__(16) float As[BM][LDA_S];
    __shared__ __align__(16) float Bs[BK][LDB_S];
    __shared__ float Epi[NWARP][16 * 16];

    int tid  = threadIdx.x;
    int wid  = tid >> 5;
    int lane = tid & 31;
    int wm   = wid / WARPS_N;
    int wn   = wid % WARPS_N;

    wmma::fragment<wmma::accumulator, 16, 16, 8, float> acc[MF][NF];
#pragma unroll
    for (int i = 0; i < MF; i++)
#pragma unroll
        for (int j = 0; j < NF; j++) wmma::fill_fragment(acc[i][j], 0.0f);

    const bool vecB = (!TRANSB) && ((ldb & 3) == 0) && (nBase + BN <= N);

    for (int kt = 0; kt < Keff; kt += BK) {
        // ---- load A tile [BM][BK] (row-major, K contiguous, float4) ----
        constexpr int A_F4 = (BM * BK) / (NT * 4);
#pragma unroll
        for (int p = 0; p < A_F4; p++) {
            int li  = tid + p * NT;
            int row = li / (BK / 4);
            int c4  = li % (BK / 4);
            float4 va = *(const float4*)&A[(long long)(mBase + row) * lda + kt + c4 * 4];
            *(float4*)&As[row][c4 * 4] = va;
        }
        // ---- load B tile [BK][BN] ----
        if (TRANSB) {
            // B logical [N,K] row-major -> Bs[k][n]
            constexpr int B_F4 = (BN * BK) / (NT * 4);
#pragma unroll
            for (int p = 0; p < B_F4; p++) {
                int li = tid + p * NT;
                int n  = li / (BK / 4);
                int kq = li % (BK / 4);
                float4 vb = *(const float4*)&B[(long long)(nBase + n) * ldb + kt + kq * 4];
                Bs[kq * 4 + 0][n] = vb.x;
                Bs[kq * 4 + 1][n] = vb.y;
                Bs[kq * 4 + 2][n] = vb.z;
                Bs[kq * 4 + 3][n] = vb.w;
            }
        } else if (vecB) {
            constexpr int B_F4 = (BK * BN) / (NT * 4);
#pragma unroll
            for (int p = 0; p < B_F4; p++) {
                int li  = tid + p * NT;
                int row = li / (BN / 4);
                int c4  = li % (BN / 4);
                float4 vb = *(const float4*)&B[(long long)(kt + row) * ldb + nBase + c4 * 4];
                *(float4*)&Bs[row][c4 * 4] = vb;
            }
        } else {
            constexpr int B_SC = (BK * BN) / NT;
#pragma unroll
            for (int p = 0; p < B_SC; p++) {
                int li  = tid + p * NT;
                int row = li / BN;
                int c   = li % BN;
                int gn  = nBase + c;
                Bs[row][c] = (gn < N) ? B[(long long)(kt + row) * ldb + gn] : 0.f;
            }
        }
        __syncthreads();

        // ---- MMA over BK in steps of 8 ----
#pragma unroll
        for (int ks = 0; ks < BK; ks += 8) {
            wmma::fragment<wmma::matrix_a, 16, 16, 8, wmma::precision::tf32, wmma::row_major> af[MF];
            wmma::fragment<wmma::matrix_b, 16, 16, 8, wmma::precision::tf32, wmma::row_major> bf[NF];
#pragma unroll
            for (int i = 0; i < MF; i++) {
                wmma::load_matrix_sync(af[i], &As[wm * WM + i * 16][ks], LDA_S);
#pragma unroll
                for (int e = 0; e < af[i].num_elements; e++)
                    af[i].x[e] = wmma::__float_to_tf32(af[i].x[e]);
            }
#pragma unroll
            for (int j = 0; j < NF; j++) {
                wmma::load_matrix_sync(bf[j], &Bs[ks][wn * WN + j * 16], LDB_S);
#pragma unroll
                for (int e = 0; e < bf[j].num_elements; e++)
                    bf[j].x[e] = wmma::__float_to_tf32(bf[j].x[e]);
            }
#pragma unroll
            for (int i = 0; i < MF; i++)
#pragma unroll
                for (int j = 0; j < NF; j++)
                    wmma::mma_sync(acc[i][j], af[i], bf[j], acc[i][j]);
        }
        __syncthreads();
    }

    // ---- epilogue via per-warp smem staging ----
    float* patch = Epi[wid];
#pragma unroll
    for (int i = 0; i < MF; i++) {
#pragma unroll
        for (int j = 0; j < NF; j++) {
            __syncwarp();
            wmma::store_matrix_sync(patch, acc[i][j], 16, wmma::mem_row_major);
            __syncwarp();
            int rbase = mBase + wm * WM + i * 16;
            int cbase = nBase + wn * WN + j * 16;
#pragma unroll
            for (int e = 0; e < 8; e++) {
                int idx = lane * 8 + e;
                int r = idx >> 4, c = idx & 15;
                int gm = rbase + r, gn = cbase + c;
                if (gn < N) {
                    float vv = patch[idx] * alpha;
                    if (bias) vv += bias[gn];
                    if (Res)  vv += Res[(long long)gm * ldc + gn];
                    if (GELU_) vv = 0.5f * vv * (1.f + erff(vv * 0.70710678118654752f));
                    C[(long long)gm * ldc + gn] = vv;
                }
            }
        }
    }
}

// ---------------- host-side orchestration ------------------------------------
extern "C" void kernel_launch(void* const* d_in, const int* in_sizes, int n_in,
                              void* d_out, int out_size)
{
    const int*   idx    = (const int*)  d_in[0];
    const float* tokemb = (const float*)d_in[1];
    const float* ln1w   = (const float*)d_in[2];
    const float* ln1b   = (const float*)d_in[3];
    const float* Wq     = (const float*)d_in[4];
    const float* bq     = (const float*)d_in[5];
    const float* Wk     = (const float*)d_in[6];
    const float* bk     = (const float*)d_in[7];
    const float* Wv     = (const float*)d_in[8];
    const float* bv     = (const float*)d_in[9];
    const float* Wp     = (const float*)d_in[10];
    const float* bp     = (const float*)d_in[11];
    const float* ln2w   = (const float*)d_in[12];
    const float* ln2b   = (const float*)d_in[13];
    const float* W1     = (const float*)d_in[14];
    const float* b1     = (const float*)d_in[15];
    const float* W2     = (const float*)d_in[16];
    const float* b2     = (const float*)d_in[17];
    const float* lnfw   = (const float*)d_in[18];
    const float* lnfb   = (const float*)d_in[19];
    const float* headw  = (const float*)d_in[20];
    float* out = (float*)d_out;

    float *x, *h, *q, *k, *v, *y, *att, *ffn;
    cudaGetSymbolAddress((void**)&x,   g_x);
    cudaGetSymbolAddress((void**)&h,   g_h);
    cudaGetSymbolAddress((void**)&q,   g_q);
    cudaGetSymbolAddress((void**)&k,   g_k);
    cudaGetSymbolAddress((void**)&v,   g_v);
    cudaGetSymbolAddress((void**)&y,   g_y);
    cudaGetSymbolAddress((void**)&att, g_att);
    cudaGetSymbolAddress((void**)&ffn, g_ffn);

    embed_kernel<<<BT * (DD / 4) / 256, 256>>>(idx, (const float4*)tokemb, (float4*)x);

    dim3 blk(256);
    for (int l = 0; l < LL; l++) {
        const float* wq = Wq + (long long)l * DD * DD;
        const float* wk = Wk + (long long)l * DD * DD;
        const float* wv = Wv + (long long)l * DD * DD;
        const float* wp = Wp + (long long)l * DD * DD;
        const float* w1 = W1 + (long long)l * DD * FF;
        const float* w2 = W2 + (long long)l * FF * DD;

        ln_kernel<<<BT, 256>>>(x, ln1w + l * DD, ln1b + l * DD, h);

        // QKV projections: [BT,D] @ [D,D]
        dim3 g1(DD / 128, BT / 128, 1);
        tc_gemm<128,128,32,64,32,false,false><<<g1, blk>>>(
            h, DD, 0, 0, wq, DD, 0, 0, q, DD, 0, 0,
            bq + l * DD, nullptr, BT, DD, DD, 1, 1.f, 0);
        tc_gemm<128,128,32,64,32,false,false><<<g1, blk>>>(
            h, DD, 0, 0, wk, DD, 0, 0, k, DD, 0, 0,
            bk + l * DD, nullptr, BT, DD, DD, 1, 1.f, 0);
        tc_gemm<128,128,32,64,32,false,false><<<g1, blk>>>(
            h, DD, 0, 0, wv, DD, 0, 0, v, DD, 0, 0,
            bv + l * DD, nullptr, BT, DD, DD, 1, 1.f, 0);

        // scores = scale * q @ k^T, batched over B*H, skip masked tiles
        dim3 g2(TT / 128, TT / 128, BB * HH);
        tc_gemm<128,128,32,64,32,true,false><<<g2, blk>>>(
            q,   DD, (long long)TT * DD, DHH,
            k,   DD, (long long)TT * DD, DHH,
            att, TT, (long long)HH * TT * TT, (long long)TT * TT,
            nullptr, nullptr, TT, TT, DHH, HH, 0.125f, 1);

        softmax_kernel<<<BB * HH * TT, 256>>>(att);

        // y = att @ v  (N = 64), K capped at causal horizon
        dim3 g3(1, TT / 128, BB * HH);
        tc_gemm<128,64,32,32,32,false,false><<<g3, blk>>>(
            att, TT, (long long)HH * TT * TT, (long long)TT * TT,
            v,   DD, (long long)TT * DD, DHH,
            y,   DD, (long long)TT * DD, DHH,
            nullptr, nullptr, TT, DHH, TT, HH, 1.f, 2);

        // x = x + y @ Wp + bp
        tc_gemm<128,128,32,64,32,false,false><<<g1, blk>>>(
            y, DD, 0, 0, wp, DD, 0, 0, x, DD, 0, 0,
            bp + l * DD, x, BT, DD, DD, 1, 1.f, 0);

        ln_kernel<<<BT, 256>>>(x, ln2w + l * DD, ln2b + l * DD, h);

        // MLP up + exact GELU
        dim3 g4(FF / 128, BT / 128, 1);
        tc_gemm<128,128,32,64,32,false,true><<<g4, blk>>>(
            h, DD, 0, 0, w1, FF, 0, 0, ffn, FF, 0, 0,
            b1 + (long long)l * FF, nullptr, BT, FF, DD, 1, 1.f, 0);

        // MLP down + residual
        tc_gemm<128,128,32,64,32,false,false><<<g1, blk>>>(
            ffn, FF, 0, 0, w2, DD, 0, 0, x, DD, 0, 0,
            b2 + l * DD, x, BT, DD, FF, 1, 1.f, 0);
    }

    ln_kernel<<<BT, 256>>>(x, lnfw, lnfb, h);

    // LM head: [BT, D] @ [D, V]  (ragged N edge -> scalar B path + predicated store)
    dim3 g5((VV + 127) / 128, BT / 128, 1);
    tc_gemm<128,128,32,64,32,false,false><<<g5, blk>>>(
        h, DD, 0, 0, headw, VV, 0, 0, out, VV, 0, 0,
        nullptr, nullptr, BT, VV, DD, 1, 1.f, 0);
}